// round 7
// baseline (speedup 1.0000x reference)
#include <cuda_runtime.h>
#include <cstdint>

// ---------------------------------------------------------------------------
// GeometricPositionalFingerprinter — Round 7: R6 math/layout + persistent
// grid-stride loop (exactly occupancy-filling grid, no wave churn).
//
// Input : pentachora [V, 5, 128] f32  (V = in_sizes[0]/640)
// Output: cantor fingerprint [V] f32
//
// 8 lanes per pentachoron (4 pentachora/warp). Lane l reads float4 columns
// {l, l+8, l+16, l+24} of each 512B vertex row -> each 8-lane group load is
// one full 128B line. Hot loop accumulates only the 10 pairwise squared
// distances; edges, volume (distance Gram det/576) and spread (centroid
// identity (5*S_v - T)/25) derive in the epilogue. 3-level XOR butterfly;
// lane 0 stores. Grid = SMs * 6 CTAs, grid-stride over pentachora.
// ---------------------------------------------------------------------------

__device__ __forceinline__ float sigmoid_pos(float x) {
    // x >= 0 always. ~2 ulp regardless of fast-math flags.
    if (x > 18.0f) return 1.0f;
    float t = -x;
    float kf = rintf(t * 1.4426950408889634f);
    float r = fmaf(-kf, 0.693145751953125f, t);
    r = fmaf(-kf, 1.428606765330187e-06f, r);
    float p = fmaf(r, 1.38888889e-3f, 8.33333333e-3f);
    p = fmaf(r, p, 4.16666667e-2f);
    p = fmaf(r, p, 1.66666667e-1f);
    p = fmaf(r, p, 0.5f);
    p = fmaf(r, p, 1.0f);
    p = fmaf(r, p, 1.0f);
    int ki = (int)kf;
    float scale = __int_as_float((ki + 127) << 23);
    float e = p * scale;
    return __fdiv_rn(1.0f, __fadd_rn(1.0f, e));
}

__global__ void __launch_bounds__(256, 6)
gpf_kernel(const float* __restrict__ pent, float* __restrict__ out, int V)
{
    const int l = threadIdx.x & 7;                     // lane within group
    const int g0 = (blockIdx.x * 256 + threadIdx.x) >> 3;
    const int gstride = (gridDim.x * 256) >> 3;        // groups per grid pass

    for (int g = g0; g < V; g += gstride) {
        const float4* __restrict__ base =
            reinterpret_cast<const float4*>(pent) + (size_t)g * 160 + l;

        float ed[10];   // pairwise squared distances, triu(5,k=1) order
#pragma unroll
        for (int i = 0; i < 10; ++i) ed[i] = 0.0f;

#pragma unroll
        for (int c = 0; c < 4; ++c) {
            float4 a[5];
#pragma unroll
            for (int v = 0; v < 5; ++v) a[v] = base[v * 32 + c * 8];

            int m = 0;
#pragma unroll
            for (int i = 0; i < 5; ++i) {
#pragma unroll
                for (int j = i + 1; j < 5; ++j) {
                    float dx = a[i].x - a[j].x;
                    float dy = a[i].y - a[j].y;
                    float dz = a[i].z - a[j].z;
                    float dw = a[i].w - a[j].w;
                    float t = ed[m];
                    t = fmaf(dx, dx, t);
                    t = fmaf(dy, dy, t);
                    t = fmaf(dz, dz, t);
                    t = fmaf(dw, dw, t);
                    ed[m] = t;
                    ++m;
                }
            }
        }

        // 3-level butterfly reduce across the 8-lane group
#pragma unroll
        for (int i = 0; i < 10; ++i) {
            ed[i] += __shfl_xor_sync(0xffffffffu, ed[i], 1);
            ed[i] += __shfl_xor_sync(0xffffffffu, ed[i], 2);
            ed[i] += __shfl_xor_sync(0xffffffffu, ed[i], 4);
        }

        // --- Edge statistics (triu(5,k=1) order) ---
        float e[10];
#pragma unroll
        for (int i = 0; i < 10; ++i) e[i] = __fsqrt_rn(fmaxf(ed[i], 0.0f));
        float esum = 0.0f;
#pragma unroll
        for (int i = 0; i < 10; ++i) esum = __fadd_rn(esum, e[i]);
        float mean_edge = __fdiv_rn(esum, 10.0f);
        float ess = 0.0f;
#pragma unroll
        for (int i = 0; i < 10; ++i) {
            float d = __fsub_rn(e[i], mean_edge);
            ess = fmaf(d, d, ess);
        }
        float std_edge = __fsqrt_rn(__fdiv_rn(ess, 9.0f));   // ddof=1
        float ratio = __fdiv_rn(std_edge, __fadd_rn(mean_edge, 1e-6f));

        // --- Vertex spread via centroid identity ---
        // S_v = sum_j dist2(v,j); T = sum of all 10; cd[v] = (5*S_v - T)/25
        float T = __fadd_rn(__fadd_rn(__fadd_rn(__fadd_rn(ed[0], ed[1]),
                                                __fadd_rn(ed[2], ed[3])),
                                      __fadd_rn(__fadd_rn(ed[4], ed[5]),
                                                __fadd_rn(ed[6], ed[7]))),
                            __fadd_rn(ed[8], ed[9]));
        float S0 = __fadd_rn(__fadd_rn(ed[0], ed[1]), __fadd_rn(ed[2], ed[3]));
        float S1 = __fadd_rn(__fadd_rn(ed[0], ed[4]), __fadd_rn(ed[5], ed[6]));
        float S2 = __fadd_rn(__fadd_rn(ed[1], ed[4]), __fadd_rn(ed[7], ed[8]));
        float S3 = __fadd_rn(__fadd_rn(ed[2], ed[5]), __fadd_rn(ed[7], ed[9]));
        float S4 = __fadd_rn(__fadd_rn(ed[3], ed[6]), __fadd_rn(ed[8], ed[9]));

        float dc[5];
        float Sv[5] = { S0, S1, S2, S3, S4 };
        float csum = 0.0f;
#pragma unroll
        for (int v = 0; v < 5; ++v) {
            float cdv = __fmul_rn(__fsub_rn(__fmul_rn(5.0f, Sv[v]), T), 0.04f);
            dc[v] = __fsqrt_rn(fmaxf(cdv, 0.0f));
            csum = __fadd_rn(csum, dc[v]);
        }
        float cmean = __fdiv_rn(csum, 5.0f);
        float css = 0.0f;
#pragma unroll
        for (int v = 0; v < 5; ++v) {
            float d = __fsub_rn(dc[v], cmean);
            css = fmaf(d, d, css);
        }
        float spread = __fsqrt_rn(__fdiv_rn(css, 4.0f));

        // --- Volume from distances via 4x4 edge-vector Gram det ---
        // G[i][j] = 0.5*(d0[i] + d0[j] - dij); vol^2 = det(G)/576
        // sigmoid(10*vol) saturates to exactly 1.0f for this data.
        float d0[4] = { ed[0], ed[1], ed[2], ed[3] };
        float G[4][4];
#pragma unroll
        for (int i = 0; i < 4; ++i) G[i][i] = d0[i];
        G[0][1] = G[1][0] = 0.5f * ((d0[0] + d0[1]) - ed[4]);
        G[0][2] = G[2][0] = 0.5f * ((d0[0] + d0[2]) - ed[5]);
        G[0][3] = G[3][0] = 0.5f * ((d0[0] + d0[3]) - ed[6]);
        G[1][2] = G[2][1] = 0.5f * ((d0[1] + d0[2]) - ed[7]);
        G[1][3] = G[3][1] = 0.5f * ((d0[1] + d0[3]) - ed[8]);
        G[2][3] = G[3][2] = 0.5f * ((d0[2] + d0[3]) - ed[9]);

        float d2233 = G[2][2] * G[3][3] - G[2][3] * G[3][2];
        float d2133 = G[2][1] * G[3][3] - G[2][3] * G[3][1];
        float d2132 = G[2][1] * G[3][2] - G[2][2] * G[3][1];
        float d2033 = G[2][0] * G[3][3] - G[2][3] * G[3][0];
        float d2032 = G[2][0] * G[3][2] - G[2][2] * G[3][0];
        float d2031 = G[2][0] * G[3][1] - G[2][1] * G[3][0];
        float c0 = G[1][1] * d2233 - G[1][2] * d2133 + G[1][3] * d2132;
        float c1 = G[1][0] * d2233 - G[1][2] * d2033 + G[1][3] * d2032;
        float c2 = G[1][0] * d2133 - G[1][1] * d2033 + G[1][3] * d2031;
        float c3 = G[1][0] * d2132 - G[1][1] * d2032 + G[1][2] * d2031;
        float det = G[0][0] * c0 - G[0][1] * c1 + G[0][2] * c2 - G[0][3] * c3;
        float vol = __fsqrt_rn(fmaxf(__fdiv_rn(det, 576.0f), 0.0f));

        // --- Seed (reference op order) ---
        float s1 = sigmoid_pos(__fmul_rn(vol, 10.0f));
        float s2 = sigmoid_pos(ratio);
        float s3 = sigmoid_pos(spread);
        float seed = __fadd_rn(__fadd_rn(__fmul_rn(s1, 0.4f),
                                         __fmul_rn(s2, 0.3f)),
                               __fmul_rn(s3, 0.3f));

        float x = fminf(fmaxf(seed, 1e-6f), 0.999999f);

        // --- Ternary Cantor digits ---
        float cantor = 0.0f;
        float factor = 0.5f;
#pragma unroll
        for (int it = 0; it < 8; ++it) {
            float xs = __fmul_rn(x, 3.0f);
            int d = (int)xs;
            x = __fsub_rn(xs, (float)d);
            if (d == 2) cantor = __fadd_rn(cantor, factor);
            factor *= 0.5f;
        }

        if (l == 0) out[g] = fminf(fmaxf(cantor, 0.0f), 1.0f);
    }
}

extern "C" void kernel_launch(void* const* d_in, const int* in_sizes, int n_in,
                              void* d_out, int out_size)
{
    const float* p = (const float*)d_in[0];
    float* out = (float*)d_out;
    int V = in_sizes[0] / 640;                 // [V, 5, 128]

    int dev = 0, sms = 148;
    cudaGetDevice(&dev);
    cudaDeviceGetAttribute(&sms, cudaDevAttrMultiProcessorCount, dev);

    // Exactly occupancy-filling persistent grid: 6 CTAs/SM (40 regs/thread).
    int grid = sms * 6;
    long long groups_needed = (long long)V;            // one 8-lane group each
    long long max_grid = (groups_needed * 8 + 255) / 256;
    if (grid > max_grid) grid = (int)max_grid;
    if (grid < 1) grid = 1;

    gpf_kernel<<<grid, 256>>>(p, out, V);
}

// round 8
// speedup vs baseline: 1.0443x; 1.0443x over previous
#include <cuda_runtime.h>
#include <cstdint>

// ---------------------------------------------------------------------------
// GeometricPositionalFingerprinter — Round 8: two-kernel split.
//
// Kernel 1 (stream): R6's flat-grid 8-lane-group streaming reduction of the
// 10 pairwise squared distances; stores them to a __device__ scratch array
// (12 floats/pentachoron, 48B stride -> float4-aligned) and retires. No
// MUFU/div/sigmoid/Cantor tail in the streaming phase.
// Kernel 2 (epilogue): 1 thread/pentachoron, 3x LDG.128 from scratch, the
// identical epilogue math (edges/volume/spread/seed/Cantor), store out[g].
//
// ed accumulation + epilogue op sequences are bit-identical to R6
// (rel_err 7.1e-5 expected to reproduce).
// ---------------------------------------------------------------------------

static constexpr int MAXV = 262144;           // VOCAB for this problem
__device__ float gpf_scratch[(size_t)MAXV * 12];

__device__ __forceinline__ float sigmoid_pos(float x) {
    // x >= 0 always. ~2 ulp regardless of fast-math flags.
    if (x > 18.0f) return 1.0f;
    float t = -x;
    float kf = rintf(t * 1.4426950408889634f);
    float r = fmaf(-kf, 0.693145751953125f, t);
    r = fmaf(-kf, 1.428606765330187e-06f, r);
    float p = fmaf(r, 1.38888889e-3f, 8.33333333e-3f);
    p = fmaf(r, p, 4.16666667e-2f);
    p = fmaf(r, p, 1.66666667e-1f);
    p = fmaf(r, p, 0.5f);
    p = fmaf(r, p, 1.0f);
    p = fmaf(r, p, 1.0f);
    int ki = (int)kf;
    float scale = __int_as_float((ki + 127) << 23);
    float e = p * scale;
    return __fdiv_rn(1.0f, __fadd_rn(1.0f, e));
}

// Epilogue from the 10 reduced pairwise squared distances (triu(5,k=1) order).
// Op-for-op identical to R6.
__device__ __forceinline__ float gpf_epilogue(const float ed[10]) {
    // --- Edge statistics ---
    float e[10];
#pragma unroll
    for (int i = 0; i < 10; ++i) e[i] = __fsqrt_rn(fmaxf(ed[i], 0.0f));
    float esum = 0.0f;
#pragma unroll
    for (int i = 0; i < 10; ++i) esum = __fadd_rn(esum, e[i]);
    float mean_edge = __fdiv_rn(esum, 10.0f);
    float ess = 0.0f;
#pragma unroll
    for (int i = 0; i < 10; ++i) {
        float d = __fsub_rn(e[i], mean_edge);
        ess = fmaf(d, d, ess);
    }
    float std_edge = __fsqrt_rn(__fdiv_rn(ess, 9.0f));   // ddof=1
    float ratio = __fdiv_rn(std_edge, __fadd_rn(mean_edge, 1e-6f));

    // --- Vertex spread via centroid identity: cd[v] = (5*S_v - T)/25 ---
    float T = __fadd_rn(__fadd_rn(__fadd_rn(__fadd_rn(ed[0], ed[1]),
                                            __fadd_rn(ed[2], ed[3])),
                                  __fadd_rn(__fadd_rn(ed[4], ed[5]),
                                            __fadd_rn(ed[6], ed[7]))),
                        __fadd_rn(ed[8], ed[9]));
    float S0 = __fadd_rn(__fadd_rn(ed[0], ed[1]), __fadd_rn(ed[2], ed[3]));
    float S1 = __fadd_rn(__fadd_rn(ed[0], ed[4]), __fadd_rn(ed[5], ed[6]));
    float S2 = __fadd_rn(__fadd_rn(ed[1], ed[4]), __fadd_rn(ed[7], ed[8]));
    float S3 = __fadd_rn(__fadd_rn(ed[2], ed[5]), __fadd_rn(ed[7], ed[9]));
    float S4 = __fadd_rn(__fadd_rn(ed[3], ed[6]), __fadd_rn(ed[8], ed[9]));

    float dc[5];
    float Sv[5] = { S0, S1, S2, S3, S4 };
    float csum = 0.0f;
#pragma unroll
    for (int v = 0; v < 5; ++v) {
        float cdv = __fmul_rn(__fsub_rn(__fmul_rn(5.0f, Sv[v]), T), 0.04f);
        dc[v] = __fsqrt_rn(fmaxf(cdv, 0.0f));
        csum = __fadd_rn(csum, dc[v]);
    }
    float cmean = __fdiv_rn(csum, 5.0f);
    float css = 0.0f;
#pragma unroll
    for (int v = 0; v < 5; ++v) {
        float d = __fsub_rn(dc[v], cmean);
        css = fmaf(d, d, css);
    }
    float spread = __fsqrt_rn(__fdiv_rn(css, 4.0f));

    // --- Volume from distances via 4x4 edge-vector Gram det ---
    float d0[4] = { ed[0], ed[1], ed[2], ed[3] };
    float G[4][4];
#pragma unroll
    for (int i = 0; i < 4; ++i) G[i][i] = d0[i];
    G[0][1] = G[1][0] = 0.5f * ((d0[0] + d0[1]) - ed[4]);
    G[0][2] = G[2][0] = 0.5f * ((d0[0] + d0[2]) - ed[5]);
    G[0][3] = G[3][0] = 0.5f * ((d0[0] + d0[3]) - ed[6]);
    G[1][2] = G[2][1] = 0.5f * ((d0[1] + d0[2]) - ed[7]);
    G[1][3] = G[3][1] = 0.5f * ((d0[1] + d0[3]) - ed[8]);
    G[2][3] = G[3][2] = 0.5f * ((d0[2] + d0[3]) - ed[9]);

    float d2233 = G[2][2] * G[3][3] - G[2][3] * G[3][2];
    float d2133 = G[2][1] * G[3][3] - G[2][3] * G[3][1];
    float d2132 = G[2][1] * G[3][2] - G[2][2] * G[3][1];
    float d2033 = G[2][0] * G[3][3] - G[2][3] * G[3][0];
    float d2032 = G[2][0] * G[3][2] - G[2][2] * G[3][0];
    float d2031 = G[2][0] * G[3][1] - G[2][1] * G[3][0];
    float c0 = G[1][1] * d2233 - G[1][2] * d2133 + G[1][3] * d2132;
    float c1 = G[1][0] * d2233 - G[1][2] * d2033 + G[1][3] * d2032;
    float c2 = G[1][0] * d2133 - G[1][1] * d2033 + G[1][3] * d2031;
    float c3 = G[1][0] * d2132 - G[1][1] * d2032 + G[1][2] * d2031;
    float det = G[0][0] * c0 - G[0][1] * c1 + G[0][2] * c2 - G[0][3] * c3;
    float vol = __fsqrt_rn(fmaxf(__fdiv_rn(det, 576.0f), 0.0f));

    // --- Seed (reference op order) ---
    float s1 = sigmoid_pos(__fmul_rn(vol, 10.0f));
    float s2 = sigmoid_pos(ratio);
    float s3 = sigmoid_pos(spread);
    float seed = __fadd_rn(__fadd_rn(__fmul_rn(s1, 0.4f), __fmul_rn(s2, 0.3f)),
                           __fmul_rn(s3, 0.3f));

    float x = fminf(fmaxf(seed, 1e-6f), 0.999999f);

    // --- Ternary Cantor digits ---
    float cantor = 0.0f;
    float factor = 0.5f;
#pragma unroll
    for (int it = 0; it < 8; ++it) {
        float xs = __fmul_rn(x, 3.0f);
        int d = (int)xs;
        x = __fsub_rn(xs, (float)d);
        if (d == 2) cantor = __fadd_rn(cantor, factor);
        factor *= 0.5f;
    }
    return fminf(fmaxf(cantor, 0.0f), 1.0f);
}

// ---- Kernel 1: pure stream + reduce -> scratch --------------------------
__global__ void __launch_bounds__(256, 6)
gpf_stream_kernel(const float* __restrict__ pent, int V)
{
    int tid = blockIdx.x * 256 + threadIdx.x;
    int g = tid >> 3;        // pentachoron index
    int l = tid & 7;         // lane within 8-lane group
    if (g >= V) return;

    const float4* __restrict__ base =
        reinterpret_cast<const float4*>(pent) + (size_t)g * 160 + l;

    float ed[10];   // pairwise squared distances, triu(5,k=1) order
#pragma unroll
    for (int i = 0; i < 10; ++i) ed[i] = 0.0f;

#pragma unroll
    for (int c = 0; c < 4; ++c) {
        float4 a[5];
#pragma unroll
        for (int v = 0; v < 5; ++v) a[v] = base[v * 32 + c * 8];

        int m = 0;
#pragma unroll
        for (int i = 0; i < 5; ++i) {
#pragma unroll
            for (int j = i + 1; j < 5; ++j) {
                float dx = a[i].x - a[j].x;
                float dy = a[i].y - a[j].y;
                float dz = a[i].z - a[j].z;
                float dw = a[i].w - a[j].w;
                float t = ed[m];
                t = fmaf(dx, dx, t);
                t = fmaf(dy, dy, t);
                t = fmaf(dz, dz, t);
                t = fmaf(dw, dw, t);
                ed[m] = t;
                ++m;
            }
        }
    }

    // 3-level butterfly reduce across the 8-lane group
#pragma unroll
    for (int i = 0; i < 10; ++i) {
        ed[i] += __shfl_xor_sync(0xffffffffu, ed[i], 1);
        ed[i] += __shfl_xor_sync(0xffffffffu, ed[i], 2);
        ed[i] += __shfl_xor_sync(0xffffffffu, ed[i], 4);
    }

    // Store ed[0..9] at scratch[g*12 + i]. Lane l writes ed[l] (SEL chain,
    // no dynamic indexing -> no local spill); lanes 0,1 also write ed[8,9].
    float v = ed[0];
    if (l == 1) v = ed[1];
    if (l == 2) v = ed[2];
    if (l == 3) v = ed[3];
    if (l == 4) v = ed[4];
    if (l == 5) v = ed[5];
    if (l == 6) v = ed[6];
    if (l == 7) v = ed[7];
    float* s = gpf_scratch + (size_t)g * 12;
    s[l] = v;
    if (l < 2) s[8 + l] = (l == 0) ? ed[8] : ed[9];
}

// ---- Kernel 2: epilogue, 1 thread per pentachoron -----------------------
__global__ void __launch_bounds__(256)
gpf_epi_kernel(float* __restrict__ out, int V)
{
    int g = blockIdx.x * 256 + threadIdx.x;
    if (g >= V) return;

    const float4* s =
        reinterpret_cast<const float4*>(gpf_scratch + (size_t)g * 12);
    float4 A = s[0], B = s[1], C = s[2];
    float ed[10] = { A.x, A.y, A.z, A.w, B.x, B.y, B.z, B.w, C.x, C.y };

    out[g] = gpf_epilogue(ed);
}

// ---- Fallback: fused single kernel (R6) for V > MAXV --------------------
__global__ void __launch_bounds__(256, 6)
gpf_fused_kernel(const float* __restrict__ pent, float* __restrict__ out, int V)
{
    int tid = blockIdx.x * 256 + threadIdx.x;
    int g = tid >> 3;
    int l = tid & 7;
    if (g >= V) return;

    const float4* __restrict__ base =
        reinterpret_cast<const float4*>(pent) + (size_t)g * 160 + l;

    float ed[10];
#pragma unroll
    for (int i = 0; i < 10; ++i) ed[i] = 0.0f;

#pragma unroll
    for (int c = 0; c < 4; ++c) {
        float4 a[5];
#pragma unroll
        for (int v = 0; v < 5; ++v) a[v] = base[v * 32 + c * 8];
        int m = 0;
#pragma unroll
        for (int i = 0; i < 5; ++i) {
#pragma unroll
            for (int j = i + 1; j < 5; ++j) {
                float dx = a[i].x - a[j].x;
                float dy = a[i].y - a[j].y;
                float dz = a[i].z - a[j].z;
                float dw = a[i].w - a[j].w;
                float t = ed[m];
                t = fmaf(dx, dx, t);
                t = fmaf(dy, dy, t);
                t = fmaf(dz, dz, t);
                t = fmaf(dw, dw, t);
                ed[m] = t;
                ++m;
            }
        }
    }
#pragma unroll
    for (int i = 0; i < 10; ++i) {
        ed[i] += __shfl_xor_sync(0xffffffffu, ed[i], 1);
        ed[i] += __shfl_xor_sync(0xffffffffu, ed[i], 2);
        ed[i] += __shfl_xor_sync(0xffffffffu, ed[i], 4);
    }

    float r = gpf_epilogue(ed);
    if (l == 0) out[g] = r;
}

extern "C" void kernel_launch(void* const* d_in, const int* in_sizes, int n_in,
                              void* d_out, int out_size)
{
    const float* p = (const float*)d_in[0];
    float* out = (float*)d_out;
    int V = in_sizes[0] / 640;                 // [V, 5, 128]

    if (V <= MAXV) {
        long long t1 = (long long)V * 8;
        int b1 = (int)((t1 + 255) / 256);
        gpf_stream_kernel<<<b1, 256>>>(p, V);
        int b2 = (V + 255) / 256;
        gpf_epi_kernel<<<b2, 256>>>(out, V);
    } else {
        long long t = (long long)V * 8;
        int b = (int)((t + 255) / 256);
        gpf_fused_kernel<<<b, 256>>>(p, out, V);
    }
}

// round 9
// speedup vs baseline: 1.1504x; 1.1017x over previous
#include <cuda_runtime.h>
#include <cstdint>

// ---------------------------------------------------------------------------
// GeometricPositionalFingerprinter — Round 9: warp-specialized fused kernel.
//
// Input : pentachora [V, 5, 128] f32  (V = in_sizes[0]/640)
// Output: cantor fingerprint [V] f32
//
// CTA = 256 threads = 8 warps, 28 pentachora per CTA.
//  - Warps 0..6 (producers): 4 pentachora each, 8 lanes/pentachoron, full
//    128B-line float4 loads, 10 pairwise-distance accumulators, 3-level
//    butterfly, SMEM stats store. NO transcendental tail.
//  - Warp 7 (consumer): after __syncthreads, threads 0..27 each run the
//    scalar epilogue (edges / volume via distance-Gram det / spread via
//    centroid identity / seed / Cantor) and store out[g].
// Producers exit right after the barrier; the consumer overlaps with other
// CTAs' streaming warps. ed + epilogue op sequences identical to R6
// (rel_err 7.1e-5 expected to reproduce).
// ---------------------------------------------------------------------------

static constexpr int PENT_PER_CTA = 28;   // 7 producer warps * 4 groups

__device__ __forceinline__ float sigmoid_pos(float x) {
    // x >= 0 always. ~2 ulp regardless of fast-math flags.
    if (x > 18.0f) return 1.0f;
    float t = -x;
    float kf = rintf(t * 1.4426950408889634f);
    float r = fmaf(-kf, 0.693145751953125f, t);
    r = fmaf(-kf, 1.428606765330187e-06f, r);
    float p = fmaf(r, 1.38888889e-3f, 8.33333333e-3f);
    p = fmaf(r, p, 4.16666667e-2f);
    p = fmaf(r, p, 1.66666667e-1f);
    p = fmaf(r, p, 0.5f);
    p = fmaf(r, p, 1.0f);
    p = fmaf(r, p, 1.0f);
    int ki = (int)kf;
    float scale = __int_as_float((ki + 127) << 23);
    float e = p * scale;
    return __fdiv_rn(1.0f, __fadd_rn(1.0f, e));
}

// Epilogue from the 10 reduced pairwise squared distances (triu(5,k=1)).
// Op-for-op identical to R6.
__device__ __forceinline__ float gpf_epilogue(const float ed[10]) {
    float e[10];
#pragma unroll
    for (int i = 0; i < 10; ++i) e[i] = __fsqrt_rn(fmaxf(ed[i], 0.0f));
    float esum = 0.0f;
#pragma unroll
    for (int i = 0; i < 10; ++i) esum = __fadd_rn(esum, e[i]);
    float mean_edge = __fdiv_rn(esum, 10.0f);
    float ess = 0.0f;
#pragma unroll
    for (int i = 0; i < 10; ++i) {
        float d = __fsub_rn(e[i], mean_edge);
        ess = fmaf(d, d, ess);
    }
    float std_edge = __fsqrt_rn(__fdiv_rn(ess, 9.0f));   // ddof=1
    float ratio = __fdiv_rn(std_edge, __fadd_rn(mean_edge, 1e-6f));

    // Vertex spread via centroid identity: cd[v] = (5*S_v - T)/25
    float T = __fadd_rn(__fadd_rn(__fadd_rn(__fadd_rn(ed[0], ed[1]),
                                            __fadd_rn(ed[2], ed[3])),
                                  __fadd_rn(__fadd_rn(ed[4], ed[5]),
                                            __fadd_rn(ed[6], ed[7]))),
                        __fadd_rn(ed[8], ed[9]));
    float S0 = __fadd_rn(__fadd_rn(ed[0], ed[1]), __fadd_rn(ed[2], ed[3]));
    float S1 = __fadd_rn(__fadd_rn(ed[0], ed[4]), __fadd_rn(ed[5], ed[6]));
    float S2 = __fadd_rn(__fadd_rn(ed[1], ed[4]), __fadd_rn(ed[7], ed[8]));
    float S3 = __fadd_rn(__fadd_rn(ed[2], ed[5]), __fadd_rn(ed[7], ed[9]));
    float S4 = __fadd_rn(__fadd_rn(ed[3], ed[6]), __fadd_rn(ed[8], ed[9]));

    float dc[5];
    float Sv[5] = { S0, S1, S2, S3, S4 };
    float csum = 0.0f;
#pragma unroll
    for (int v = 0; v < 5; ++v) {
        float cdv = __fmul_rn(__fsub_rn(__fmul_rn(5.0f, Sv[v]), T), 0.04f);
        dc[v] = __fsqrt_rn(fmaxf(cdv, 0.0f));
        csum = __fadd_rn(csum, dc[v]);
    }
    float cmean = __fdiv_rn(csum, 5.0f);
    float css = 0.0f;
#pragma unroll
    for (int v = 0; v < 5; ++v) {
        float d = __fsub_rn(dc[v], cmean);
        css = fmaf(d, d, css);
    }
    float spread = __fsqrt_rn(__fdiv_rn(css, 4.0f));

    // Volume via 4x4 edge-vector Gram det; sigmoid(10*vol) saturates to 1.0f.
    float d0[4] = { ed[0], ed[1], ed[2], ed[3] };
    float G[4][4];
#pragma unroll
    for (int i = 0; i < 4; ++i) G[i][i] = d0[i];
    G[0][1] = G[1][0] = 0.5f * ((d0[0] + d0[1]) - ed[4]);
    G[0][2] = G[2][0] = 0.5f * ((d0[0] + d0[2]) - ed[5]);
    G[0][3] = G[3][0] = 0.5f * ((d0[0] + d0[3]) - ed[6]);
    G[1][2] = G[2][1] = 0.5f * ((d0[1] + d0[2]) - ed[7]);
    G[1][3] = G[3][1] = 0.5f * ((d0[1] + d0[3]) - ed[8]);
    G[2][3] = G[3][2] = 0.5f * ((d0[2] + d0[3]) - ed[9]);

    float d2233 = G[2][2] * G[3][3] - G[2][3] * G[3][2];
    float d2133 = G[2][1] * G[3][3] - G[2][3] * G[3][1];
    float d2132 = G[2][1] * G[3][2] - G[2][2] * G[3][1];
    float d2033 = G[2][0] * G[3][3] - G[2][3] * G[3][0];
    float d2032 = G[2][0] * G[3][2] - G[2][2] * G[3][0];
    float d2031 = G[2][0] * G[3][1] - G[2][1] * G[3][0];
    float c0 = G[1][1] * d2233 - G[1][2] * d2133 + G[1][3] * d2132;
    float c1 = G[1][0] * d2233 - G[1][2] * d2033 + G[1][3] * d2032;
    float c2 = G[1][0] * d2133 - G[1][1] * d2033 + G[1][3] * d2031;
    float c3 = G[1][0] * d2132 - G[1][1] * d2032 + G[1][2] * d2031;
    float det = G[0][0] * c0 - G[0][1] * c1 + G[0][2] * c2 - G[0][3] * c3;
    float vol = __fsqrt_rn(fmaxf(__fdiv_rn(det, 576.0f), 0.0f));

    float s1 = sigmoid_pos(__fmul_rn(vol, 10.0f));
    float s2 = sigmoid_pos(ratio);
    float s3 = sigmoid_pos(spread);
    float seed = __fadd_rn(__fadd_rn(__fmul_rn(s1, 0.4f), __fmul_rn(s2, 0.3f)),
                           __fmul_rn(s3, 0.3f));

    float x = fminf(fmaxf(seed, 1e-6f), 0.999999f);

    float cantor = 0.0f;
    float factor = 0.5f;
#pragma unroll
    for (int it = 0; it < 8; ++it) {
        float xs = __fmul_rn(x, 3.0f);
        int d = (int)xs;
        x = __fsub_rn(xs, (float)d);
        if (d == 2) cantor = __fadd_rn(cantor, factor);
        factor *= 0.5f;
    }
    return fminf(fmaxf(cantor, 0.0f), 1.0f);
}

__global__ void __launch_bounds__(256, 6)
gpf_ws_kernel(const float* __restrict__ pent, float* __restrict__ out, int V)
{
    __shared__ float sed[PENT_PER_CTA][12];   // 10 stats + pad

    const int tid  = threadIdx.x;
    const int wid  = tid >> 5;                // warp id 0..7
    const int lane = tid & 31;

    if (wid < 7) {
        // ---------------- producer: stream 4 pentachora ----------------
        const int p = wid * 4 + (lane >> 3);  // group within CTA, 0..27
        const int l = lane & 7;               // lane within 8-lane group
        const int g = blockIdx.x * PENT_PER_CTA + p;

        if (g < V) {
            const float4* __restrict__ base =
                reinterpret_cast<const float4*>(pent) + (size_t)g * 160 + l;

            float ed[10];
#pragma unroll
            for (int i = 0; i < 10; ++i) ed[i] = 0.0f;

#pragma unroll
            for (int c = 0; c < 4; ++c) {
                float4 a[5];
#pragma unroll
                for (int v = 0; v < 5; ++v) a[v] = base[v * 32 + c * 8];

                int m = 0;
#pragma unroll
                for (int i = 0; i < 5; ++i) {
#pragma unroll
                    for (int j = i + 1; j < 5; ++j) {
                        float dx = a[i].x - a[j].x;
                        float dy = a[i].y - a[j].y;
                        float dz = a[i].z - a[j].z;
                        float dw = a[i].w - a[j].w;
                        float t = ed[m];
                        t = fmaf(dx, dx, t);
                        t = fmaf(dy, dy, t);
                        t = fmaf(dz, dz, t);
                        t = fmaf(dw, dw, t);
                        ed[m] = t;
                        ++m;
                    }
                }
            }

            // 3-level butterfly across the 8-lane group
#pragma unroll
            for (int i = 0; i < 10; ++i) {
                ed[i] += __shfl_xor_sync(0xffffffffu, ed[i], 1);
                ed[i] += __shfl_xor_sync(0xffffffffu, ed[i], 2);
                ed[i] += __shfl_xor_sync(0xffffffffu, ed[i], 4);
            }

            // Lane l stores ed[l]; lanes 0,1 also store ed[8],ed[9].
            float v = ed[0];
            if (l == 1) v = ed[1];
            if (l == 2) v = ed[2];
            if (l == 3) v = ed[3];
            if (l == 4) v = ed[4];
            if (l == 5) v = ed[5];
            if (l == 6) v = ed[6];
            if (l == 7) v = ed[7];
            sed[p][l] = v;
            if (l < 2) sed[p][8 + l] = (l == 0) ? ed[8] : ed[9];
        }

        __syncthreads();
        // producers exit here
    } else {
        // ---------------- consumer: 28 epilogues ----------------
        __syncthreads();

        if (lane < PENT_PER_CTA) {
            int g = blockIdx.x * PENT_PER_CTA + lane;
            if (g < V) {
                float ed[10];
#pragma unroll
                for (int i = 0; i < 10; ++i) ed[i] = sed[lane][i];
                out[g] = gpf_epilogue(ed);
            }
        }
    }
}

extern "C" void kernel_launch(void* const* d_in, const int* in_sizes, int n_in,
                              void* d_out, int out_size)
{
    const float* p = (const float*)d_in[0];
    float* out = (float*)d_out;
    int V = in_sizes[0] / 640;                 // [V, 5, 128]
    int blocks = (V + PENT_PER_CTA - 1) / PENT_PER_CTA;
    gpf_ws_kernel<<<blocks, 256>>>(p, out, V);
}